// round 15
// baseline (speedup 1.0000x reference)
#include <cuda_runtime.h>
#include <cuda_fp16.h>
#include <math.h>
#include <stdint.h>

// GAT layer. Single stream, 6 launches.
//   kprep: attention-fold (last block) + zero g_cnt/g_spub
//   kedge: histogram of dst, 4 edges/thread (blocks [0,GH)) + attention scalars
//   scan1: single-kernel decoupled-lookback exclusive scan -> g_off/g_cur
//   k1:    scatter prologue (4 edges/thread, hidden behind GEMM) +
//          h_msg = X @ W1^T + b1 (tf32 mma, 64-row tile, 2 blocks/SM) -> fp16
//   kagg:  warp-per-node fused softmax+aggregate (fp16 gather, MLP 8)
//   k4:    out = leaky((X+h) + (X*h) @ W2^T + b2) (tf32 mma, 64-row tile)

#define MAXN 100096
#define MAXE 1600000
#define TS 132

__device__ __half g_hmsg[MAXN * 128];
__device__ float  g_hneigh[MAXN * 128];
__device__ float  g_ssrc[MAXN];
__device__ float  g_sdst[MAXN];
__device__ __align__(16) float g_u[260];
__device__ int    g_cnt[MAXN];
__device__ int    g_off[MAXN + 1];
__device__ int    g_cur[MAXN];
__device__ int    g_es[MAXE];
__device__ int    g_spub[128];

__device__ __forceinline__ float leaky_f(float x) { return x >= 0.f ? x : 0.01f * x; }

__device__ __forceinline__ uint32_t f2tf(float f) {
    uint32_t u;
    asm("cvt.rna.tf32.f32 %0, %1;" : "=r"(u) : "f"(f));
    return u;
}

#define MMA_TF32(c, a, b0, b1)                                                   \
    asm volatile("mma.sync.aligned.m16n8k8.row.col.f32.tf32.tf32.f32 "           \
                 "{%0,%1,%2,%3}, {%4,%5,%6,%7}, {%8,%9}, {%0,%1,%2,%3};"         \
                 : "+f"((c)[0]), "+f"((c)[1]), "+f"((c)[2]), "+f"((c)[3])        \
                 : "r"((a)[0]), "r"((a)[1]), "r"((a)[2]), "r"((a)[3]),           \
                   "r"(b0), "r"(b1))

// ---------------------------------------------------------------------------
__global__ __launch_bounds__(512) void kprep(const float* __restrict__ Watt,
                                             const float* __restrict__ batt,
                                             const float* __restrict__ a,
                                             int N, int NZ)
{
    const int bid = blockIdx.x, t = threadIdx.x;
    if (bid < NZ) {
        int i = bid * 512 + t;
        if (i < N) g_cnt[i] = 0;
        return;
    }

    __shared__ float pus[4][128];
    __shared__ float pud[4][128];
    __shared__ float red[256];
    int k = t & 127;
    int seg = t >> 7;

    if (t < 128) {
        red[t] = batt[t] * a[t];
        red[128 + t] = batt[t] * a[128 + t];
        g_spub[t] = 0;
    }

    float us = 0.f, ud = 0.f;
    #pragma unroll
    for (int oo = 0; oo < 32; oo++) {
        int o = seg * 32 + oo;
        float w = Watt[o * 128 + k];
        us += w * a[o];
        ud += w * a[128 + o];
    }
    pus[seg][k] = us;
    pud[seg][k] = ud;
    __syncthreads();

    if (seg == 0) {
        float s = 0.f, dd = 0.f;
        #pragma unroll
        for (int i = 0; i < 4; i++) { s += pus[i][k]; dd += pud[i][k]; }
        g_u[k] = s;
        g_u[128 + k] = dd;
    }
    if (t == 0) {
        float cs = 0.f, cd = 0.f;
        for (int i = 0; i < 128; i++) { cs += red[i]; cd += red[128 + i]; }
        g_u[256] = cs;
        g_u[257] = cd;
    }
}

// ---------------------------------------------------------------------------
// kedge: blocks [0,GH): histogram, 4 edges/thread (independent atomics).
// blocks [GH,..): attention scalars, one warp per node.
// ---------------------------------------------------------------------------
__global__ __launch_bounds__(256) void kedge(const int* __restrict__ dst,
                                             const float* __restrict__ X,
                                             int E, int N, int GH)
{
    const int t = threadIdx.x;
    if ((int)blockIdx.x < GH) {
        int e0 = (blockIdx.x * 256 + t) * 4;
        if (e0 + 3 < E) {
            int4 d = *(const int4*)(dst + e0);
            atomicAdd(&g_cnt[d.x], 1);
            atomicAdd(&g_cnt[d.y], 1);
            atomicAdd(&g_cnt[d.z], 1);
            atomicAdd(&g_cnt[d.w], 1);
        } else {
            for (int e = e0; e < E; e++) atomicAdd(&g_cnt[__ldg(dst + e)], 1);
        }
        return;
    }
    int nb = blockIdx.x - GH;
    int n = nb * 8 + (t >> 5);
    if (n >= N) return;
    int lane = t & 31;
    float4 v = ((const float4*)X)[n * 32 + lane];
    float4 us = ((const float4*)g_u)[lane];
    float4 ud = ((const float4*)(g_u + 128))[lane];
    float as = v.x * us.x + v.y * us.y + v.z * us.z + v.w * us.w;
    float ad = v.x * ud.x + v.y * ud.y + v.z * ud.z + v.w * ud.w;
    #pragma unroll
    for (int o = 16; o > 0; o >>= 1) {
        as += __shfl_xor_sync(0xffffffffu, as, o);
        ad += __shfl_xor_sync(0xffffffffu, ad, o);
    }
    if (lane == 0) {
        g_ssrc[n] = as + g_u[256];
        g_sdst[n] = ad + g_u[257];
    }
}

// ---------------------------------------------------------------------------
__global__ __launch_bounds__(1024) void scan1(int N)
{
    __shared__ int sh[1024];
    __shared__ int s_excl;
    const int tid = threadIdx.x;
    const int bid = blockIdx.x;
    const int g = bid * 1024 + tid;

    int v = (g < N) ? g_cnt[g] : 0;
    sh[tid] = v;
    __syncthreads();
    for (int d = 1; d < 1024; d <<= 1) {
        int t = (tid >= d) ? sh[tid - d] : 0;
        __syncthreads();
        sh[tid] += t;
        __syncthreads();
    }

    if (tid == 0)
        atomicExch(&g_spub[bid], (int)(0x80000000u | (unsigned)sh[1023]));

    if (tid < 32) {
        int sum = 0;
        for (int p = tid; p < bid; p += 32) {
            int val;
            do { val = ((volatile int*)g_spub)[p]; } while (val == 0);
            sum += val & 0x7fffffff;
        }
        #pragma unroll
        for (int o = 16; o > 0; o >>= 1) sum += __shfl_xor_sync(0xffffffffu, sum, o);
        if (tid == 0) s_excl = sum;
    }
    __syncthreads();

    int excl = s_excl;
    if (g < N) {
        int o = excl + sh[tid] - v;
        g_off[g] = o;
        g_cur[g] = o;
    }
    if (bid == (int)gridDim.x - 1 && tid == 0)
        g_off[N] = excl + sh[1023];
}

// ---------------------------------------------------------------------------
// k1: scatter prologue + tf32 GEMM (64-row tile, 2 blocks/SM).
// ---------------------------------------------------------------------------
#define GEMM_SMEM ((64 + 128) * TS * 4)

__global__ __launch_bounds__(256, 2) void k1_msg(const float* __restrict__ X,
                                                 const float* __restrict__ W1,
                                                 const float* __restrict__ b1,
                                                 const int* __restrict__ src,
                                                 const int* __restrict__ dst,
                                                 int N, int E)
{
    extern __shared__ uint32_t smu[];
    uint32_t* Xs = smu;            // 64*TS
    uint32_t* Ws = smu + 64 * TS;  // 128*TS
    const int tid = threadIdx.x;
    const int bn = blockIdx.x * 64;

    // Scatter prologue (store-and-forget; overlapped with the GEMM below).
    {
        int e0 = (blockIdx.x * 256 + tid) * 4;
        if (e0 + 3 < E) {
            int4 d = *(const int4*)(dst + e0);
            int4 s = *(const int4*)(src + e0);
            g_es[atomicAdd(&g_cur[d.x], 1)] = s.x;
            g_es[atomicAdd(&g_cur[d.y], 1)] = s.y;
            g_es[atomicAdd(&g_cur[d.z], 1)] = s.z;
            g_es[atomicAdd(&g_cur[d.w], 1)] = s.w;
        } else {
            for (int e = e0; e < E; e++) {
                int d = __ldg(dst + e);
                g_es[atomicAdd(&g_cur[d], 1)] = __ldg(src + e);
            }
        }
    }

    for (int i = tid; i < 64 * 32; i += 256) {
        int r = i >> 5, c4 = i & 31;
        int n = bn + r;
        float4 v = (n < N) ? ((const float4*)X)[n * 32 + c4] : make_float4(0.f, 0.f, 0.f, 0.f);
        uint32_t* p = Xs + r * TS + (c4 >> 1) * 8 + (c4 & 1);
        p[0] = f2tf(v.x); p[2] = f2tf(v.y); p[4] = f2tf(v.z); p[6] = f2tf(v.w);
    }
    for (int i = tid; i < 128 * 32; i += 256) {
        int o = i >> 5, c4 = i & 31;
        float4 v = *(const float4*)(W1 + o * 128 + c4 * 4);
        uint32_t* p = Ws + o * TS + (c4 >> 1) * 8 + (c4 & 1);
        p[0] = f2tf(v.x); p[2] = f2tf(v.y); p[4] = f2tf(v.z); p[6] = f2tf(v.w);
    }
    __syncthreads();

    const int wid = tid >> 5, lane = tid & 31;
    const int gid = lane >> 2, tig = lane & 3;
    const int mb = (wid >> 2) * 32;
    const int nb = (wid & 3) * 32;

    float acc[2][4][4];
    #pragma unroll
    for (int m = 0; m < 2; m++)
        #pragma unroll
        for (int n = 0; n < 4; n++)
            #pragma unroll
            for (int j = 0; j < 4; j++) acc[m][n][j] = 0.f;

    #pragma unroll 4
    for (int ks = 0; ks < 16; ks++) {
        const int kb = ks * 8 + tig * 2;
        uint32_t a[2][4];
        #pragma unroll
        for (int mt = 0; mt < 2; mt++) {
            int r0 = mb + mt * 16 + gid;
            uint2 ua = *(const uint2*)(Xs + r0 * TS + kb);
            uint2 ub = *(const uint2*)(Xs + (r0 + 8) * TS + kb);
            a[mt][0] = ua.x; a[mt][1] = ub.x; a[mt][2] = ua.y; a[mt][3] = ub.y;
        }
        #pragma unroll
        for (int nt = 0; nt < 4; nt++) {
            int o = nb + nt * 8 + gid;
            uint2 w = *(const uint2*)(Ws + o * TS + kb);
            MMA_TF32(acc[0][nt], a[0], w.x, w.y);
            MMA_TF32(acc[1][nt], a[1], w.x, w.y);
        }
    }

    #pragma unroll
    for (int nt = 0; nt < 4; nt++) {
        int col = nb + nt * 8 + tig * 2;
        float2 bb = *(const float2*)(b1 + col);
        #pragma unroll
        for (int mt = 0; mt < 2; mt++) {
            int row = bn + mb + mt * 16 + gid;
            if (row < N)
                *(__half2*)(g_hmsg + row * 128 + col) =
                    __floats2half2_rn(acc[mt][nt][0] + bb.x, acc[mt][nt][1] + bb.y);
            if (row + 8 < N)
                *(__half2*)(g_hmsg + (row + 8) * 128 + col) =
                    __floats2half2_rn(acc[mt][nt][2] + bb.x, acc[mt][nt][3] + bb.y);
        }
    }
}

// ---------------------------------------------------------------------------
__global__ __launch_bounds__(256) void kagg(int N)
{
    const int d = blockIdx.x * 8 + (threadIdx.x >> 5);
    if (d >= N) return;
    const int lane = threadIdx.x & 31;
    const int rs = g_off[d], re = g_off[d + 1];
    const float sdst_d = g_sdst[d];

    float4 acc = make_float4(0.f, 0.f, 0.f, 0.f);
    float wsum = 0.f;

    for (int c = rs; c < re; c += 32) {
        int cnt = re - c; if (cnt > 32) cnt = 32;
        int s = (lane < cnt) ? g_es[c + lane] : 0;
        float w = (lane < cnt) ? expf(leaky_f(g_ssrc[s] + sdst_d)) : 0.f;
        wsum += w;

        int j = 0;
        for (; j + 8 <= cnt; j += 8) {
            int si[8]; float wi[8]; uint2 ui[8];
            #pragma unroll
            for (int t = 0; t < 8; t++) {
                si[t] = __shfl_sync(0xffffffffu, s, j + t);
                wi[t] = __shfl_sync(0xffffffffu, w, j + t);
            }
            #pragma unroll
            for (int t = 0; t < 8; t++)
                ui[t] = ((const uint2*)(g_hmsg + si[t] * 128))[lane];
            #pragma unroll
            for (int t = 0; t < 8; t++) {
                float2 lo = __half22float2(*(__half2*)&ui[t].x);
                float2 hi = __half22float2(*(__half2*)&ui[t].y);
                acc.x += wi[t] * lo.x; acc.y += wi[t] * lo.y;
                acc.z += wi[t] * hi.x; acc.w += wi[t] * hi.y;
            }
        }
        for (; j < cnt; j++) {
            int sj = __shfl_sync(0xffffffffu, s, j);
            float wj = __shfl_sync(0xffffffffu, w, j);
            uint2 u = ((const uint2*)(g_hmsg + sj * 128))[lane];
            float2 lo = __half22float2(*(__half2*)&u.x);
            float2 hi = __half22float2(*(__half2*)&u.y);
            acc.x += wj * lo.x; acc.y += wj * lo.y;
            acc.z += wj * hi.x; acc.w += wj * hi.y;
        }
    }

    #pragma unroll
    for (int o = 16; o > 0; o >>= 1) wsum += __shfl_xor_sync(0xffffffffu, wsum, o);
    float inv = 1.f / (wsum + 1e-9f);
    acc.x *= inv; acc.y *= inv; acc.z *= inv; acc.w *= inv;
    ((float4*)g_hneigh)[d * 32 + lane] = acc;
}

// ---------------------------------------------------------------------------
__global__ __launch_bounds__(256, 2) void k4_out(const float* __restrict__ X,
                                                 const float* __restrict__ W2,
                                                 const float* __restrict__ b2,
                                                 float* __restrict__ out, int N)
{
    extern __shared__ uint32_t smu[];
    uint32_t* Ps = smu;            // 64*TS, (x*h) tf32 fragment order
    uint32_t* Ws = smu + 64 * TS;  // 128*TS
    const int tid = threadIdx.x;
    const int bn = blockIdx.x * 64;

    for (int i = tid; i < 64 * 32; i += 256) {
        int r = i >> 5, c4 = i & 31;
        int n = bn + r;
        float4 x = (n < N) ? ((const float4*)X)[n * 32 + c4] : make_float4(0.f, 0.f, 0.f, 0.f);
        float4 h = (n < N) ? ((const float4*)g_hneigh)[n * 32 + c4] : make_float4(0.f, 0.f, 0.f, 0.f);
        uint32_t* p = Ps + r * TS + (c4 >> 1) * 8 + (c4 & 1);
        p[0] = f2tf(x.x * h.x); p[2] = f2tf(x.y * h.y);
        p[4] = f2tf(x.z * h.z); p[6] = f2tf(x.w * h.w);
    }
    for (int i = tid; i < 128 * 32; i += 256) {
        int o = i >> 5, c4 = i & 31;
        float4 v = *(const float4*)(W2 + o * 128 + c4 * 4);
        uint32_t* p = Ws + o * TS + (c4 >> 1) * 8 + (c4 & 1);
        p[0] = f2tf(v.x); p[2] = f2tf(v.y); p[4] = f2tf(v.z); p[6] = f2tf(v.w);
    }
    __syncthreads();

    const int wid = tid >> 5, lane = tid & 31;
    const int gid = lane >> 2, tig = lane & 3;
    const int mb = (wid >> 2) * 32;
    const int nb = (wid & 3) * 32;

    float acc[2][4][4];
    #pragma unroll
    for (int m = 0; m < 2; m++)
        #pragma unroll
        for (int n = 0; n < 4; n++)
            #pragma unroll
            for (int j = 0; j < 4; j++) acc[m][n][j] = 0.f;

    #pragma unroll 4
    for (int ks = 0; ks < 16; ks++) {
        const int kb = ks * 8 + tig * 2;
        uint32_t a[2][4];
        #pragma unroll
        for (int mt = 0; mt < 2; mt++) {
            int r0 = mb + mt * 16 + gid;
            uint2 ua = *(const uint2*)(Ps + r0 * TS + kb);
            uint2 ub = *(const uint2*)(Ps + (r0 + 8) * TS + kb);
            a[mt][0] = ua.x; a[mt][1] = ub.x; a[mt][2] = ua.y; a[mt][3] = ub.y;
        }
        #pragma unroll
        for (int nt = 0; nt < 4; nt++) {
            int o = nb + nt * 8 + gid;
            uint2 w = *(const uint2*)(Ws + o * TS + kb);
            MMA_TF32(acc[0][nt], a[0], w.x, w.y);
            MMA_TF32(acc[1][nt], a[1], w.x, w.y);
        }
    }

    #pragma unroll
    for (int nt = 0; nt < 4; nt++) {
        int col = nb + nt * 8 + tig * 2;
        float2 bb = *(const float2*)(b2 + col);
        #pragma unroll
        for (int mt = 0; mt < 2; mt++) {
            #pragma unroll
            for (int half = 0; half < 2; half++) {
                int row = bn + mb + mt * 16 + gid + half * 8;
                if (row < N) {
                    float2 x = *(const float2*)(X + row * 128 + col);
                    float2 h = *(const float2*)(g_hneigh + row * 128 + col);
                    float r0 = x.x + h.x + acc[mt][nt][half * 2] + bb.x;
                    float r1 = x.y + h.y + acc[mt][nt][half * 2 + 1] + bb.y;
                    *(float2*)(out + row * 128 + col) =
                        make_float2(leaky_f(r0), leaky_f(r1));
                }
            }
        }
    }
}

// ---------------------------------------------------------------------------
extern "C" void kernel_launch(void* const* d_in, const int* in_sizes, int n_in,
                              void* d_out, int out_size)
{
    const int*   indices = (const int*)d_in[0];
    const float* X       = (const float*)d_in[1];
    const float* Watt    = (const float*)d_in[3];
    const float* batt    = (const float*)d_in[4];
    const float* W1      = (const float*)d_in[5];
    const float* b1      = (const float*)d_in[6];
    const float* W2      = (const float*)d_in[7];
    const float* b2      = (const float*)d_in[8];
    const float* a       = (const float*)d_in[9];
    float* out = (float*)d_out;

    const int E = in_sizes[0] / 2;
    const int N = in_sizes[1] / 128;
    const int* src = indices;
    const int* dst = indices + E;

    const int NZ = (N + 511) / 512;
    const int GH = (E + 1023) / 1024;
    const int GS = (N + 7) / 8;
    const int NB = (N + 1023) / 1024;
    int G1 = (N + 63) / 64;
    const int GSC = (E + 1023) / 1024;
    if (GSC > G1) G1 = GSC;   // ensure scatter covers all edges

    cudaFuncSetAttribute(k1_msg, cudaFuncAttributeMaxDynamicSharedMemorySize, GEMM_SMEM);
    cudaFuncSetAttribute(k4_out, cudaFuncAttributeMaxDynamicSharedMemorySize, GEMM_SMEM);

    kprep<<<NZ + 1, 512>>>(Watt, batt, a, N, NZ);
    kedge<<<GH + GS, 256>>>(dst, X, E, N, GH);
    scan1<<<NB, 1024>>>(N);
    k1_msg<<<G1, 256, GEMM_SMEM>>>(X, W1, b1, src, dst, N, E);
    kagg<<<(N + 7) / 8, 256>>>(N);
    k4_out<<<(N + 63) / 64, 256, GEMM_SMEM>>>(X, W2, b2, out, N);
}

// round 17
// speedup vs baseline: 1.2383x; 1.2383x over previous
#include <cuda_runtime.h>
#include <cuda_fp16.h>
#include <math.h>
#include <stdint.h>

// GAT layer. Single stream, 7 launches.
//   kprep: attention-fold (last block) + zero g_cnt/g_spub
//   kedge: histogram of dst + attention scalars (fp32 X)
//   scan1: decoupled-lookback exclusive scan -> g_off/g_cur
//   kscat: counting-sort scatter
//   k1:    h_msg = X @ W1^T + b1  (fp16 mma m16n8k16, 64-row tile, 3 blk/SM)
//   kagg:  warp-per-node fused softmax+aggregate (fp16 gather, MLP 8)
//   k4:    out = leaky((X+h) + (X*h) @ W2^T + b2)  (fp16 mma)

#define MAXN 100096
#define MAXE 1600000
#define HTS 68   // smem row stride in uint32 (half2) words: 64 data + 4 pad

__device__ __half g_hmsg[MAXN * 128];
__device__ float  g_hneigh[MAXN * 128];
__device__ float  g_ssrc[MAXN];
__device__ float  g_sdst[MAXN];
__device__ __align__(16) float g_u[260];
__device__ int    g_cnt[MAXN];
__device__ int    g_off[MAXN + 1];
__device__ int    g_cur[MAXN];
__device__ int    g_es[MAXE];
__device__ int    g_spub[128];

__device__ __forceinline__ float leaky_f(float x) { return x >= 0.f ? x : 0.01f * x; }

// fragment-order position of half2-word w (0..63) within a row:
// thread (gid,tig) reads words (ks*8+tig, ks*8+tig+4) as one uint2.
__device__ __forceinline__ int fragpos(int w) {
    return ((w >> 3) << 3) + ((w & 3) << 1) + ((w >> 2) & 1);
}

#define MMA_F16(c, a0, a1, a2, a3, b0, b1)                                       \
    asm volatile("mma.sync.aligned.m16n8k16.row.col.f32.f16.f16.f32 "            \
                 "{%0,%1,%2,%3}, {%4,%5,%6,%7}, {%8,%9}, {%0,%1,%2,%3};"         \
                 : "+f"((c)[0]), "+f"((c)[1]), "+f"((c)[2]), "+f"((c)[3])        \
                 : "r"(a0), "r"(a1), "r"(a2), "r"(a3), "r"(b0), "r"(b1))

// ---------------------------------------------------------------------------
__global__ __launch_bounds__(512) void kprep(const float* __restrict__ Watt,
                                             const float* __restrict__ batt,
                                             const float* __restrict__ a,
                                             int N, int NZ)
{
    const int bid = blockIdx.x, t = threadIdx.x;
    if (bid < NZ) {
        int i = bid * 512 + t;
        if (i < N) g_cnt[i] = 0;
        return;
    }

    __shared__ float pus[4][128];
    __shared__ float pud[4][128];
    __shared__ float red[256];
    int k = t & 127;
    int seg = t >> 7;

    if (t < 128) {
        red[t] = batt[t] * a[t];
        red[128 + t] = batt[t] * a[128 + t];
        g_spub[t] = 0;
    }

    float us = 0.f, ud = 0.f;
    #pragma unroll
    for (int oo = 0; oo < 32; oo++) {
        int o = seg * 32 + oo;
        float w = Watt[o * 128 + k];
        us += w * a[o];
        ud += w * a[128 + o];
    }
    pus[seg][k] = us;
    pud[seg][k] = ud;
    __syncthreads();

    if (seg == 0) {
        float s = 0.f, dd = 0.f;
        #pragma unroll
        for (int i = 0; i < 4; i++) { s += pus[i][k]; dd += pud[i][k]; }
        g_u[k] = s;
        g_u[128 + k] = dd;
    }
    if (t == 0) {
        float cs = 0.f, cd = 0.f;
        for (int i = 0; i < 128; i++) { cs += red[i]; cd += red[128 + i]; }
        g_u[256] = cs;
        g_u[257] = cd;
    }
}

// ---------------------------------------------------------------------------
__global__ __launch_bounds__(256) void kedge(const int* __restrict__ dst,
                                             const float* __restrict__ X,
                                             int E, int N, int GH)
{
    const int t = threadIdx.x;
    if ((int)blockIdx.x < GH) {
        int e = blockIdx.x * 256 + t;
        if (e < E) atomicAdd(&g_cnt[__ldg(dst + e)], 1);
        return;
    }
    int nb = blockIdx.x - GH;
    int n = nb * 8 + (t >> 5);
    if (n >= N) return;
    int lane = t & 31;
    float4 v = ((const float4*)X)[n * 32 + lane];
    float4 us = ((const float4*)g_u)[lane];
    float4 ud = ((const float4*)(g_u + 128))[lane];
    float as = v.x * us.x + v.y * us.y + v.z * us.z + v.w * us.w;
    float ad = v.x * ud.x + v.y * ud.y + v.z * ud.z + v.w * ud.w;
    #pragma unroll
    for (int o = 16; o > 0; o >>= 1) {
        as += __shfl_xor_sync(0xffffffffu, as, o);
        ad += __shfl_xor_sync(0xffffffffu, ad, o);
    }
    if (lane == 0) {
        g_ssrc[n] = as + g_u[256];
        g_sdst[n] = ad + g_u[257];
    }
}

// ---------------------------------------------------------------------------
__global__ __launch_bounds__(1024) void scan1(int N)
{
    __shared__ int sh[1024];
    __shared__ int s_excl;
    const int tid = threadIdx.x;
    const int bid = blockIdx.x;
    const int g = bid * 1024 + tid;

    int v = (g < N) ? g_cnt[g] : 0;
    sh[tid] = v;
    __syncthreads();
    for (int d = 1; d < 1024; d <<= 1) {
        int t = (tid >= d) ? sh[tid - d] : 0;
        __syncthreads();
        sh[tid] += t;
        __syncthreads();
    }

    if (tid == 0)
        atomicExch(&g_spub[bid], (int)(0x80000000u | (unsigned)sh[1023]));

    if (tid < 32) {
        int sum = 0;
        for (int p = tid; p < bid; p += 32) {
            int val;
            do { val = ((volatile int*)g_spub)[p]; } while (val == 0);
            sum += val & 0x7fffffff;
        }
        #pragma unroll
        for (int o = 16; o > 0; o >>= 1) sum += __shfl_xor_sync(0xffffffffu, sum, o);
        if (tid == 0) s_excl = sum;
    }
    __syncthreads();

    int excl = s_excl;
    if (g < N) {
        int o = excl + sh[tid] - v;
        g_off[g] = o;
        g_cur[g] = o;
    }
    if (bid == (int)gridDim.x - 1 && tid == 0)
        g_off[N] = excl + sh[1023];
}

// ---------------------------------------------------------------------------
__global__ void kscat(const int* __restrict__ src, const int* __restrict__ dst, int E)
{
    int e = blockIdx.x * 256 + threadIdx.x;
    if (e < E) {
        int d = __ldg(dst + e);
        int pos = atomicAdd(&g_cur[d], 1);
        g_es[pos] = __ldg(src + e);
    }
}

// ---------------------------------------------------------------------------
// k1: fp16 GEMM, 64-row x 128-out tile, 52 KB smem -> 3 blocks/SM.
// 8 warps in 2m x 4n grid, warp tile 32x32, k=16 per mma.
// ---------------------------------------------------------------------------
#define GEMM_SMEM ((64 + 128) * HTS * 4)

__global__ __launch_bounds__(256, 3) void k1_msg(const float* __restrict__ X,
                                                 const float* __restrict__ W1,
                                                 const float* __restrict__ b1,
                                                 int N)
{
    extern __shared__ uint32_t smu[];
    uint32_t* Xs = smu;             // 64*HTS half2 words
    uint32_t* Ws = smu + 64 * HTS;  // 128*HTS
    const int tid = threadIdx.x;
    const int bn = blockIdx.x * 64;

    for (int i = tid; i < 64 * 32; i += 256) {
        int r = i >> 5, c4 = i & 31;
        int n = bn + r;
        float4 v = (n < N) ? ((const float4*)X)[n * 32 + c4] : make_float4(0.f, 0.f, 0.f, 0.f);
        __half2 h0 = __floats2half2_rn(v.x, v.y);
        __half2 h1 = __floats2half2_rn(v.z, v.w);
        uint32_t* base = Xs + r * HTS;
        base[fragpos(2 * c4)]     = *(uint32_t*)&h0;
        base[fragpos(2 * c4 + 1)] = *(uint32_t*)&h1;
    }
    for (int i = tid; i < 128 * 32; i += 256) {
        int o = i >> 5, c4 = i & 31;
        float4 v = *(const float4*)(W1 + o * 128 + c4 * 4);
        __half2 h0 = __floats2half2_rn(v.x, v.y);
        __half2 h1 = __floats2half2_rn(v.z, v.w);
        uint32_t* base = Ws + o * HTS;
        base[fragpos(2 * c4)]     = *(uint32_t*)&h0;
        base[fragpos(2 * c4 + 1)] = *(uint32_t*)&h1;
    }
    __syncthreads();

    const int wid = tid >> 5, lane = tid & 31;
    const int gid = lane >> 2, tig = lane & 3;
    const int mb = (wid >> 2) * 32;
    const int nb = (wid & 3) * 32;

    float acc[2][4][4];
    #pragma unroll
    for (int m = 0; m < 2; m++)
        #pragma unroll
        for (int n = 0; n < 4; n++)
            #pragma unroll
            for (int j = 0; j < 4; j++) acc[m][n][j] = 0.f;

    #pragma unroll
    for (int ks = 0; ks < 8; ks++) {
        const int kb = ks * 8 + tig * 2;
        uint32_t a[2][4];
        #pragma unroll
        for (int mt = 0; mt < 2; mt++) {
            int r0 = mb + mt * 16 + gid;
            uint2 ua = *(const uint2*)(Xs + r0 * HTS + kb);
            uint2 ub = *(const uint2*)(Xs + (r0 + 8) * HTS + kb);
            a[mt][0] = ua.x; a[mt][1] = ub.x; a[mt][2] = ua.y; a[mt][3] = ub.y;
        }
        #pragma unroll
        for (int nt = 0; nt < 4; nt++) {
            int o = nb + nt * 8 + gid;
            uint2 w = *(const uint2*)(Ws + o * HTS + kb);
            MMA_F16(acc[0][nt], a[0][0], a[0][1], a[0][2], a[0][3], w.x, w.y);
            MMA_F16(acc[1][nt], a[1][0], a[1][1], a[1][2], a[1][3], w.x, w.y);
        }
    }

    #pragma unroll
    for (int nt = 0; nt < 4; nt++) {
        int col = nb + nt * 8 + tig * 2;
        float2 bb = *(const float2*)(b1 + col);
        #pragma unroll
        for (int mt = 0; mt < 2; mt++) {
            int row = bn + mb + mt * 16 + gid;
            if (row < N)
                *(__half2*)(g_hmsg + row * 128 + col) =
                    __floats2half2_rn(acc[mt][nt][0] + bb.x, acc[mt][nt][1] + bb.y);
            if (row + 8 < N)
                *(__half2*)(g_hmsg + (row + 8) * 128 + col) =
                    __floats2half2_rn(acc[mt][nt][2] + bb.x, acc[mt][nt][3] + bb.y);
        }
    }
}

// ---------------------------------------------------------------------------
__global__ __launch_bounds__(256) void kagg(int N)
{
    const int d = blockIdx.x * 8 + (threadIdx.x >> 5);
    if (d >= N) return;
    const int lane = threadIdx.x & 31;
    const int rs = g_off[d], re = g_off[d + 1];
    const float sdst_d = g_sdst[d];

    float4 acc = make_float4(0.f, 0.f, 0.f, 0.f);
    float wsum = 0.f;

    for (int c = rs; c < re; c += 32) {
        int cnt = re - c; if (cnt > 32) cnt = 32;
        int s = (lane < cnt) ? g_es[c + lane] : 0;
        float w = (lane < cnt) ? expf(leaky_f(g_ssrc[s] + sdst_d)) : 0.f;
        wsum += w;

        int j = 0;
        for (; j + 8 <= cnt; j += 8) {
            int si[8]; float wi[8]; uint2 ui[8];
            #pragma unroll
            for (int t = 0; t < 8; t++) {
                si[t] = __shfl_sync(0xffffffffu, s, j + t);
                wi[t] = __shfl_sync(0xffffffffu, w, j + t);
            }
            #pragma unroll
            for (int t = 0; t < 8; t++)
                ui[t] = ((const uint2*)(g_hmsg + si[t] * 128))[lane];
            #pragma unroll
            for (int t = 0; t < 8; t++) {
                float2 lo = __half22float2(*(__half2*)&ui[t].x);
                float2 hi = __half22float2(*(__half2*)&ui[t].y);
                acc.x += wi[t] * lo.x; acc.y += wi[t] * lo.y;
                acc.z += wi[t] * hi.x; acc.w += wi[t] * hi.y;
            }
        }
        for (; j < cnt; j++) {
            int sj = __shfl_sync(0xffffffffu, s, j);
            float wj = __shfl_sync(0xffffffffu, w, j);
            uint2 u = ((const uint2*)(g_hmsg + sj * 128))[lane];
            float2 lo = __half22float2(*(__half2*)&u.x);
            float2 hi = __half22float2(*(__half2*)&u.y);
            acc.x += wj * lo.x; acc.y += wj * lo.y;
            acc.z += wj * hi.x; acc.w += wj * hi.y;
        }
    }

    #pragma unroll
    for (int o = 16; o > 0; o >>= 1) wsum += __shfl_xor_sync(0xffffffffu, wsum, o);
    float inv = 1.f / (wsum + 1e-9f);
    acc.x *= inv; acc.y *= inv; acc.z *= inv; acc.w *= inv;
    ((float4*)g_hneigh)[d * 32 + lane] = acc;
}

// ---------------------------------------------------------------------------
__global__ __launch_bounds__(256, 3) void k4_out(const float* __restrict__ X,
                                                 const float* __restrict__ W2,
                                                 const float* __restrict__ b2,
                                                 float* __restrict__ out, int N)
{
    extern __shared__ uint32_t smu[];
    uint32_t* Ps = smu;             // 64*HTS, (x*h) fp16 fragment order
    uint32_t* Ws = smu + 64 * HTS;  // 128*HTS
    const int tid = threadIdx.x;
    const int bn = blockIdx.x * 64;

    for (int i = tid; i < 64 * 32; i += 256) {
        int r = i >> 5, c4 = i & 31;
        int n = bn + r;
        float4 x = (n < N) ? ((const float4*)X)[n * 32 + c4] : make_float4(0.f, 0.f, 0.f, 0.f);
        float4 h = (n < N) ? ((const float4*)g_hneigh)[n * 32 + c4] : make_float4(0.f, 0.f, 0.f, 0.f);
        __half2 h0 = __floats2half2_rn(x.x * h.x, x.y * h.y);
        __half2 h1 = __floats2half2_rn(x.z * h.z, x.w * h.w);
        uint32_t* base = Ps + r * HTS;
        base[fragpos(2 * c4)]     = *(uint32_t*)&h0;
        base[fragpos(2 * c4 + 1)] = *(uint32_t*)&h1;
    }
    for (int i = tid; i < 128 * 32; i += 256) {
        int o = i >> 5, c4 = i & 31;
        float4 v = *(const float4*)(W2 + o * 128 + c4 * 4);
        __half2 h0 = __floats2half2_rn(v.x, v.y);
        __half2 h1 = __floats2half2_rn(v.z, v.w);
        uint32_t* base = Ws + o * HTS;
        base[fragpos(2 * c4)]     = *(uint32_t*)&h0;
        base[fragpos(2 * c4 + 1)] = *(uint32_t*)&h1;
    }
    __syncthreads();

    const int wid = tid >> 5, lane = tid & 31;
    const int gid = lane >> 2, tig = lane & 3;
    const int mb = (wid >> 2) * 32;
    const int nb = (wid & 3) * 32;

    float acc[2][4][4];
    #pragma unroll
    for (int m = 0; m < 2; m++)
        #pragma unroll
        for (int n = 0; n < 4; n++)
            #pragma unroll
            for (int j = 0; j < 4; j++) acc[m][n][j] = 0.f;

    #pragma unroll
    for (int ks = 0; ks < 8; ks++) {
        const int kb = ks * 8 + tig * 2;
        uint32_t a[2][4];
        #pragma unroll
        for (int mt = 0; mt < 2; mt++) {
            int r0 = mb + mt * 16 + gid;
            uint2 ua = *(const uint2*)(Ps + r0 * HTS + kb);
            uint2 ub = *(const uint2*)(Ps + (r0 + 8) * HTS + kb);
            a[mt][0] = ua.x; a[mt][1] = ub.x; a[mt][2] = ua.y; a[mt][3] = ub.y;
        }
        #pragma unroll
        for (int nt = 0; nt < 4; nt++) {
            int o = nb + nt * 8 + gid;
            uint2 w = *(const uint2*)(Ws + o * HTS + kb);
            MMA_F16(acc[0][nt], a[0][0], a[0][1], a[0][2], a[0][3], w.x, w.y);
            MMA_F16(acc[1][nt], a[1][0], a[1][1], a[1][2], a[1][3], w.x, w.y);
        }
    }

    #pragma unroll
    for (int nt = 0; nt < 4; nt++) {
        int col = nb + nt * 8 + tig * 2;
        float2 bb = *(const float2*)(b2 + col);
        #pragma unroll
        for (int mt = 0; mt < 2; mt++) {
            #pragma unroll
            for (int half = 0; half < 2; half++) {
                int row = bn + mb + mt * 16 + gid + half * 8;
                if (row < N) {
                    float2 x = *(const float2*)(X + row * 128 + col);
                    float2 h = *(const float2*)(g_hneigh + row * 128 + col);
                    float r0 = x.x + h.x + acc[mt][nt][half * 2] + bb.x;
                    float r1 = x.y + h.y + acc[mt][nt][half * 2 + 1] + bb.y;
                    *(float2*)(out + row * 128 + col) =
                        make_float2(leaky_f(r0), leaky_f(r1));
                }
            }
        }
    }
}

// ---------------------------------------------------------------------------
extern "C" void kernel_launch(void* const* d_in, const int* in_sizes, int n_in,
                              void* d_out, int out_size)
{
    const int*   indices = (const int*)d_in[0];
    const float* X       = (const float*)d_in[1];
    const float* Watt    = (const float*)d_in[3];
    const float* batt    = (const float*)d_in[4];
    const float* W1      = (const float*)d_in[5];
    const float* b1      = (const float*)d_in[6];
    const float* W2      = (const float*)d_in[7];
    const float* b2      = (const float*)d_in[8];
    const float* a       = (const float*)d_in[9];
    float* out = (float*)d_out;

    const int E = in_sizes[0] / 2;
    const int N = in_sizes[1] / 128;
    const int* src = indices;
    const int* dst = indices + E;

    const int NZ = (N + 511) / 512;
    const int GH = (E + 255) / 256;
    const int GS = (N + 7) / 8;
    const int NB = (N + 1023) / 1024;

    cudaFuncSetAttribute(k1_msg, cudaFuncAttributeMaxDynamicSharedMemorySize, GEMM_SMEM);
    cudaFuncSetAttribute(k4_out, cudaFuncAttributeMaxDynamicSharedMemorySize, GEMM_SMEM);

    kprep<<<NZ + 1, 512>>>(Watt, batt, a, N, NZ);
    kedge<<<GH + GS, 256>>>(dst, X, E, N, GH);
    scan1<<<NB, 1024>>>(N);
    kscat<<<(E + 255) / 256, 256>>>(src, dst, E);
    k1_msg<<<(N + 63) / 64, 256, GEMM_SMEM>>>(X, W1, b1, N);
    kagg<<<(N + 7) / 8, 256>>>(N);
    k4_out<<<(N + 63) / 64, 256, GEMM_SMEM>>>(X, W2, b2, out, N);
}